// round 1
// baseline (speedup 1.0000x reference)
#include <cuda_runtime.h>
#include <math.h>

#define NQ     16
#define DIM    65536
#define BATCH  64
#define NCLS   23
#define CHUNK  4096      // 2^12 amps per chunk
#define NCHUNK 16
#define TPB    256
#define APT    16        // amps per thread (CHUNK/TPB)
#define PPT    8         // pairs per thread per gate

// 32 MB statevector scratch + per-chunk measurement partials
__device__ float2 g_state[BATCH * DIM];
__device__ float  g_part[BATCH][NCHUNK][NQ];

// ---------------------------------------------------------------------------
__global__ void k_init() {
    int i = blockIdx.x * blockDim.x + threadIdx.x;
    int stride = gridDim.x * blockDim.x;
    for (; i < BATCH * DIM; i += stride) {
        g_state[i] = make_float2(((i & (DIM - 1)) == 0) ? 1.0f : 0.0f, 0.0f);
    }
}

// local chunk index -> global index within a sample
__device__ __forceinline__ int gmap(int local, int cid, bool typeB) {
    return typeB ? ((local & 0xFF) | (cid << 8) | ((local >> 8) << 12))
                 : (local | (cid << 12));
}

// fused (Rot ∘ RX) 2x2 gate on local bit lb, all amps in shared chunk
__device__ __forceinline__ void gateU(float2* s, int lb,
                                      float2 u0, float2 u1, float2 u2, float2 u3) {
    int t = threadIdx.x;
#pragma unroll
    for (int k = 0; k < PPT; k++) {
        int p  = t + TPB * k;                                   // pair id 0..2047
        int i0 = ((p >> lb) << (lb + 1)) | (p & ((1 << lb) - 1));
        int i1 = i0 | (1 << lb);
        float2 a0 = s[i0], a1 = s[i1];
        float2 n0, n1;
        n0.x = u0.x * a0.x - u0.y * a0.y + u1.x * a1.x - u1.y * a1.y;
        n0.y = u0.x * a0.y + u0.y * a0.x + u1.x * a1.y + u1.y * a1.x;
        n1.x = u2.x * a0.x - u2.y * a0.y + u3.x * a1.x - u3.y * a1.y;
        n1.y = u2.x * a0.y + u2.y * a0.x + u3.x * a1.y + u3.y * a1.x;
        s[i0] = n0;
        s[i1] = n1;
    }
}

// CRX: RX(theta) on pair bit lb, applied only where global ctrl bit cb == 1
__device__ __forceinline__ void gateCRX(float2* s, int lb, int cb,
                                        float cs, float sn, int cid, bool typeB) {
    int t = threadIdx.x;
#pragma unroll
    for (int k = 0; k < PPT; k++) {
        int p  = t + TPB * k;
        int i0 = ((p >> lb) << (lb + 1)) | (p & ((1 << lb) - 1));
        int i1 = i0 | (1 << lb);
        int g0 = gmap(i0, cid, typeB);
        if ((g0 >> cb) & 1) {
            float2 a0 = s[i0], a1 = s[i1];
            float2 n0 = make_float2(cs * a0.x + sn * a1.y, cs * a0.y - sn * a1.x);
            float2 n1 = make_float2(cs * a1.x + sn * a0.y, cs * a1.y - sn * a0.x);
            s[i0] = n0;
            s[i1] = n1;
        }
    }
}

// ---------------------------------------------------------------------------
__global__ __launch_bounds__(TPB) void k_pass(
    int pass,
    const float* __restrict__ x,  const float* __restrict__ w0,
    const float* __restrict__ x0, const float* __restrict__ w1,
    const float* __restrict__ x1)
{
    __shared__ float2 s[CHUNK];       // 32 KB chunk
    __shared__ float2 sU[NQ][4];      // fused U per global bit
    __shared__ float2 sC[NQ];         // (cos,sin) for CRX per ctrl bit
    __shared__ float  sred[8][NQ];    // cross-warp measurement reduce

    const int t   = threadIdx.x;
    const int cid = blockIdx.x;       // chunk id
    const int b   = blockIdx.y;       // sample
    const bool typeB = (pass == 2 || pass == 4 || pass == 6 || pass == 8);

    // ---- per-pass gate-matrix prep (threads 0..15, one per global bit) ----
    if (t < NQ) {
        const int bit = t;
        const int q   = 15 - bit;                 // wire index (wire 0 = MSB)
        const int uLayer = (pass >= 4) ? 1 : 0;   // U gates: L0 in P1-P2, L1 in P4-P5
        const int cLayer = (pass <= 4) ? 0 : 1;   // CRX: L0 through P4, L1 after

        // fused U = Rot(w[q]) @ RX(x[b][q])
        const float* w = (uLayer ? w1 : w0) + q * 3;
        float xq = x[b * NQ + q];
        float sx, cx;  sincosf(0.5f * xq, &sx, &cx);
        float phi = w[0], th = w[1], om = w[2];
        float sth, cth; sincosf(0.5f * th, &sth, &cth);
        float sp, cp;   sincosf(0.5f * (phi + om), &sp, &cp);
        float sm, cm;   sincosf(0.5f * (phi - om), &sm, &cm);
        // Rot elements
        float2 ra = make_float2( cp * cth, -sp * cth);
        float2 rb = make_float2(-cm * sth, -sm * sth);
        float2 rc = make_float2( cm * sth, -sm * sth);
        float2 rd = make_float2( cp * cth,  sp * cth);
        // U = Rot * RX,  RX = [[cx, -i sx], [-i sx, cx]]
        sU[bit][0] = make_float2(ra.x * cx + rb.y * sx,  ra.y * cx - rb.x * sx);
        sU[bit][1] = make_float2(ra.y * sx + rb.x * cx, -ra.x * sx + rb.y * cx);
        sU[bit][2] = make_float2(rc.x * cx + rd.y * sx,  rc.y * cx - rd.x * sx);
        sU[bit][3] = make_float2(rc.y * sx + rd.x * cx, -rc.x * sx + rd.y * cx);

        // CRX for ctrl bit == bit: wire q_ctrl = 15 - bit, angle xc[q_ctrl]
        const float* xc = cLayer ? x1 : x0;
        float a2 = xc[15 - bit];
        float ss, cs; sincosf(0.5f * a2, &ss, &cs);
        sC[bit] = make_float2(cs, ss);
    }

    // ---- load chunk (coalesced) ----
    const float2* gs = g_state + (size_t)b * DIM;
#pragma unroll
    for (int k = 0; k < APT; k++) {
        int local = t + TPB * k;
        s[local] = gs[gmap(local, cid, typeB)];
    }
    __syncthreads();

#define GU(gbit, lb) { float2 u0=sU[gbit][0],u1=sU[gbit][1],u2=sU[gbit][2],u3=sU[gbit][3]; \
                       gateU(s,(lb),u0,u1,u2,u3); __syncthreads(); }
#define GC(cb, lb)   { float2 c2=sC[cb]; gateCRX(s,(lb),(cb),c2.x,c2.y,cid,typeB); __syncthreads(); }

    if (pass == 1) {                       // A: U layer0, bits 0..11
        for (int bb = 0; bb < 12; bb++) GU(bb, bb);
    } else if (pass == 2) {                // B: U layer0 bits 12..15; CRX L0 (15,14)(14,13)(13,12)
        GU(12, 8) GU(13, 9) GU(14, 10) GU(15, 11)
        GC(15, 10) GC(14, 9) GC(13, 8)
    } else if (pass == 3) {                // A: CRX L0 (12,11)...(1,0)
        for (int cb = 12; cb >= 1; cb--) GC(cb, cb - 1);
    } else if (pass == 4) {                // B: CRX L0 (0,15); U layer1 bits 12..15 and 0..7
        GC(0, 11)
        GU(12, 8) GU(13, 9) GU(14, 10) GU(15, 11)
        for (int bb = 0; bb < 8; bb++) GU(bb, bb);
    } else if (pass == 5) {                // A: U layer1 bits 8..11
        GU(8, 8) GU(9, 9) GU(10, 10) GU(11, 11)
    } else if (pass == 6) {                // B: CRX L1 (15,14)(14,13)(13,12)
        GC(15, 10) GC(14, 9) GC(13, 8)
    } else if (pass == 7) {                // A: CRX L1 (12,11)...(1,0)
        for (int cb = 12; cb >= 1; cb--) GC(cb, cb - 1);
    } else {                               // pass 8, B: CRX L1 (0,15); then measurement
        GC(0, 11)
    }

    // ---- store chunk back ----
    float2* gso = g_state + (size_t)b * DIM;
#pragma unroll
    for (int k = 0; k < APT; k++) {
        int local = t + TPB * k;
        gso[gmap(local, cid, typeB)] = s[local];
    }

    // ---- measurement (pass 8 only): per-bit signed probability sums ----
    if (pass == 8) {
        float acc[NQ];
#pragma unroll
        for (int i = 0; i < NQ; i++) acc[i] = 0.0f;
#pragma unroll
        for (int k = 0; k < APT; k++) {
            int local = t + TPB * k;
            int g = gmap(local, cid, true);
            float2 a = s[local];
            float p2 = a.x * a.x + a.y * a.y;
#pragma unroll
            for (int bit = 0; bit < NQ; bit++)
                acc[bit] += ((g >> bit) & 1) ? -p2 : p2;
        }
        // warp reduce each of the 16 sums
#pragma unroll
        for (int i = 0; i < NQ; i++) {
#pragma unroll
            for (int o = 16; o >= 1; o >>= 1)
                acc[i] += __shfl_down_sync(0xFFFFFFFFu, acc[i], o);
        }
        __syncthreads();
        int warp = t >> 5, lane = t & 31;
        if (lane == 0) {
#pragma unroll
            for (int i = 0; i < NQ; i++) sred[warp][i] = acc[i];
        }
        __syncthreads();
        if (t < NQ) {
            float sum = 0.0f;
#pragma unroll
            for (int wI = 0; wI < 8; wI++) sum += sred[wI][t];
            g_part[b][cid][t] = sum;   // indexed by BIT
        }
    }
#undef GU
#undef GC
}

// ---------------------------------------------------------------------------
__global__ void k_final(const float* __restrict__ fc_w,
                        const float* __restrict__ fc_b,
                        float* __restrict__ out) {
    int b = blockIdx.x;
    int t = threadIdx.x;
    __shared__ float feats[NQ];
    __shared__ float logits[NCLS];
    if (t < NQ) {
        float sum = 0.0f;
        int bit = 15 - t;                    // wire t measures bit (15 - t)
#pragma unroll
        for (int c = 0; c < NCHUNK; c++) sum += g_part[b][c][bit];
        feats[t] = sum;
    }
    __syncthreads();
    if (t < NCLS) {
        float z = fc_b[t];
#pragma unroll
        for (int wI = 0; wI < NQ; wI++) z += feats[wI] * fc_w[t * NQ + wI];
        logits[t] = z;
    }
    __syncthreads();
    if (t == 0) {
        float mx = logits[0];
        for (int c = 1; c < NCLS; c++) mx = fmaxf(mx, logits[c]);
        float sum = 0.0f;
        for (int c = 0; c < NCLS; c++) sum += expf(logits[c] - mx);
        float l = logf(sum) + mx;
        for (int c = 0; c < NCLS; c++) out[b * NCLS + c] = logits[c] - l;
    }
}

// ---------------------------------------------------------------------------
extern "C" void kernel_launch(void* const* d_in, const int* in_sizes, int n_in,
                              void* d_out, int out_size) {
    const float* x    = (const float*)d_in[0];   // (64,16)
    const float* w0   = (const float*)d_in[1];   // (16,3)
    const float* x0   = (const float*)d_in[2];   // (16,)
    const float* w1   = (const float*)d_in[3];   // (16,3)
    const float* x1   = (const float*)d_in[4];   // (16,)
    const float* fc_w = (const float*)d_in[5];   // (23,16)
    const float* fc_b = (const float*)d_in[6];   // (23,)
    float* out = (float*)d_out;                  // (64,23)

    k_init<<<2048, 256>>>();
    dim3 grid(NCHUNK, BATCH);
    for (int p = 1; p <= 8; p++)
        k_pass<<<grid, TPB>>>(p, x, w0, x0, w1, x1);
    k_final<<<BATCH, 32>>>(fc_w, fc_b, out);
}

// round 3
// speedup vs baseline: 3.5394x; 3.5394x over previous
#include <cuda_runtime.h>
#include <math.h>

#define NQ     16
#define DIM    65536
#define BATCH  64
#define NCLS   23
#define CHUNK  4096
#define NCHUNK 16
#define TPB    256

typedef unsigned long long ull;

// 32 MB statevector scratch (amp = packed (re,im) float2 in a u64) + measurement partials
__device__ ull   g_state[BATCH * DIM];
__device__ float g_part[BATCH][NCHUNK][NQ];

// ---------------- packed f32x2 helpers ----------------
__device__ __forceinline__ ull pk(float x, float y) {
    ull r; asm("mov.b64 %0,{%1,%2};" : "=l"(r) : "f"(x), "f"(y)); return r;
}
__device__ __forceinline__ ull bc(float x) { return pk(x, x); }
__device__ __forceinline__ void upk(ull a, float& x, float& y) {
    asm("mov.b64 {%0,%1},%2;" : "=f"(x), "=f"(y) : "l"(a));
}
__device__ __forceinline__ ull f2mul(ull a, ull b) {
    ull r; asm("mul.rn.f32x2 %0,%1,%2;" : "=l"(r) : "l"(a), "l"(b)); return r;
}
__device__ __forceinline__ ull f2fma(ull a, ull b, ull c) {
    ull r; asm("fma.rn.f32x2 %0,%1,%2,%3;" : "=l"(r) : "l"(a), "l"(b), "l"(c)); return r;
}
__device__ __forceinline__ ull swaph(ull a) { return (a << 32) | (a >> 32); }
// i * a  = (-im, re)
__device__ __forceinline__ ull cpi(ull a) { return swaph(a) ^ 0x0000000080000000ull; }
// -i * a = (im, -re)
__device__ __forceinline__ ull cmi(ull a) { return swaph(a) ^ 0x8000000000000000ull; }

// ---------------- register gates (16 amps / thread = 4 hypercube bits) -----
// fused 2x2 U on register bit RB
template<int RB>
__device__ __forceinline__ void gU(ull* a, const float2* u) {
    float2 U0 = u[0], U1 = u[1], U2 = u[2], U3 = u[3];
    ull u0x = bc(U0.x), u0y = bc(U0.y), u1x = bc(U1.x), u1y = bc(U1.y);
    ull u2x = bc(U2.x), u2y = bc(U2.y), u3x = bc(U3.x), u3y = bc(U3.y);
#pragma unroll
    for (int m = 0; m < 8; m++) {
        int i0 = ((m >> RB) << (RB + 1)) | (m & ((1 << RB) - 1));
        int i1 = i0 | (1 << RB);
        ull a0 = a[i0], a1 = a[i1];
        ull c0 = cpi(a0), c1 = cpi(a1);
        a[i0] = f2fma(c1, u1y, f2fma(a1, u1x, f2fma(c0, u0y, f2mul(a0, u0x))));
        a[i1] = f2fma(c1, u3y, f2fma(a1, u3x, f2fma(c0, u2y, f2mul(a0, u2x))));
    }
}
// plain RX on register bit RB (used when ctrl is a uniform/thread predicate)
template<int RB>
__device__ __forceinline__ void gRX(ull* a, float2 c) {
    ull cp = bc(c.x), sp = bc(c.y);
#pragma unroll
    for (int m = 0; m < 8; m++) {
        int i0 = ((m >> RB) << (RB + 1)) | (m & ((1 << RB) - 1));
        int i1 = i0 | (1 << RB);
        ull a0 = a[i0], a1 = a[i1];
        a[i0] = f2fma(cmi(a1), sp, f2mul(a0, cp));
        a[i1] = f2fma(cmi(a0), sp, f2mul(a1, cp));
    }
}
// CRX: ctrl = register bit CB, target = register bit RB
template<int RB, int CB>
__device__ __forceinline__ void gCRX(ull* a, float2 c) {
    ull cp = bc(c.x), sp = bc(c.y);
#pragma unroll
    for (int m = 0; m < 8; m++) {
        int i0 = ((m >> RB) << (RB + 1)) | (m & ((1 << RB) - 1));
        if (!((i0 >> CB) & 1)) continue;       // compile-time predicate
        int i1 = i0 | (1 << RB);
        ull a0 = a[i0], a1 = a[i1];
        a[i0] = f2fma(cmi(a1), sp, f2mul(a0, cp));
        a[i1] = f2fma(cmi(a0), sp, f2mul(a1, cp));
    }
}

// ---------------- layouts & transposes ----------------
// layout 0 (H): reg bits = local 8-11 :  i = r*256 + t
// layout 1 (L): reg bits = local 0-3  :  i = t*16 + r
// layout 2 (M): reg bits = local 4-7  :  i = (t>>4)*256 + r*16 + (t&15)
template<int L>
__device__ __forceinline__ int lidx(int r, int t) {
    return L == 0 ? ((r << 8) | t)
         : L == 1 ? ((t << 4) | r)
                  : (((t >> 4) << 8) | (r << 4) | (t & 15));
}
__device__ __forceinline__ int swz(int i) { return i ^ ((i >> 4) & 0xF); }

template<int F, int T>
__device__ __forceinline__ void xpose(ull* a, ull* s, int t) {
    __syncthreads();
#pragma unroll
    for (int r = 0; r < 16; r++) s[swz(lidx<F>(r, t))] = a[r];
    __syncthreads();
#pragma unroll
    for (int r = 0; r < 16; r++) a[r] = s[swz(lidx<T>(r, t))];
}

// local -> global index maps
__device__ __forceinline__ int gA(int i, int cid) { return i | (cid << 12); }
__device__ __forceinline__ int gB(int i, int cid) { return (i & 0xFF) | (cid << 8) | ((i >> 8) << 12); }

// ---------------------------------------------------------------------------
template<int PASS>
__global__ __launch_bounds__(TPB) void k_pass(
    const float* __restrict__ x,  const float* __restrict__ w0,
    const float* __restrict__ x0, const float* __restrict__ w1,
    const float* __restrict__ x1)
{
    __shared__ ull    s[CHUNK];      // 32 KB transpose buffer
    __shared__ float2 sU[NQ][4];     // fused (Rot∘RX) per global bit, pass's U-layer
    __shared__ float2 sC0[NQ], sC1[NQ];
    __shared__ float  sred[8][NQ];

    const int t   = threadIdx.x;
    const int cid = blockIdx.x;
    const int b   = blockIdx.y;

    if (t < NQ) {
        const int bit = t;
        const int q   = 15 - bit;               // wire (wire 0 = MSB)
        const float* w = ((PASS >= 3) ? w1 : w0) + q * 3;
        float xq = x[b * NQ + q];
        float sx, cx; sincosf(0.5f * xq, &sx, &cx);
        float phi = w[0], th = w[1], om = w[2];
        float sth, cth; sincosf(0.5f * th, &sth, &cth);
        float sp, cp;   sincosf(0.5f * (phi + om), &sp, &cp);
        float sm, cm;   sincosf(0.5f * (phi - om), &sm, &cm);
        float2 ra = make_float2( cp * cth, -sp * cth);
        float2 rb = make_float2(-cm * sth, -sm * sth);
        float2 rc = make_float2( cm * sth, -sm * sth);
        float2 rd = make_float2( cp * cth,  sp * cth);
        sU[bit][0] = make_float2(ra.x * cx + rb.y * sx,  ra.y * cx - rb.x * sx);
        sU[bit][1] = make_float2(ra.y * sx + rb.x * cx, -ra.x * sx + rb.y * cx);
        sU[bit][2] = make_float2(rc.x * cx + rd.y * sx,  rc.y * cx - rd.x * sx);
        sU[bit][3] = make_float2(rc.y * sx + rd.x * cx, -rc.x * sx + rd.y * cx);
        float a0s, a0c; sincosf(0.5f * x0[q], &a0s, &a0c);
        sC0[bit] = make_float2(a0c, a0s);
        float a1s, a1c; sincosf(0.5f * x1[q], &a1s, &a1c);
        sC1[bit] = make_float2(a1c, a1s);
    }
    __syncthreads();

    ull a[16];
    ull* gs = g_state + (size_t)b * DIM;

    if constexpr (PASS == 1) {
        // B map. Init |0..0>, U0 on global {12-15}, CRX L0 (15,14)(14,13)(13,12),
        // then U0 on {0-3}, {4-7}.
#pragma unroll
        for (int r = 0; r < 16; r++) a[r] = 0ull;
        if (t == 0 && cid == 0) a[0] = pk(1.0f, 0.0f);
        gU<0>(a, sU[12]); gU<1>(a, sU[13]); gU<2>(a, sU[14]); gU<3>(a, sU[15]);
        gCRX<2, 3>(a, sC0[15]); gCRX<1, 2>(a, sC0[14]); gCRX<0, 1>(a, sC0[13]);
        xpose<0, 1>(a, s, t);
        gU<0>(a, sU[0]); gU<1>(a, sU[1]); gU<2>(a, sU[2]); gU<3>(a, sU[3]);
        xpose<1, 2>(a, s, t);
        gU<0>(a, sU[4]); gU<1>(a, sU[5]); gU<2>(a, sU[6]); gU<3>(a, sU[7]);
#pragma unroll
        for (int r = 0; r < 16; r++) gs[gB(lidx<2>(r, t), cid)] = a[r];
    }
    else if constexpr (PASS == 2 || PASS == 4) {
        // A map. U layer on global {8-11}, then CRX chain (12,11)(11,10)...(1,0).
        const float2* C = (PASS == 2) ? sC0 : sC1;
#pragma unroll
        for (int r = 0; r < 16; r++) a[r] = gs[gA(lidx<0>(r, t), cid)];
        gU<0>(a, sU[8]); gU<1>(a, sU[9]); gU<2>(a, sU[10]); gU<3>(a, sU[11]);
        if (cid & 1) gRX<3>(a, C[12]);                       // ctrl = global bit 12 (chunk)
        gCRX<2, 3>(a, C[11]); gCRX<1, 2>(a, C[10]); gCRX<0, 1>(a, C[9]);
        xpose<0, 2>(a, s, t);
        if ((t >> 4) & 1) gRX<3>(a, C[8]);                   // ctrl = global bit 8 (thread)
        gCRX<2, 3>(a, C[7]); gCRX<1, 2>(a, C[6]); gCRX<0, 1>(a, C[5]);
        xpose<2, 1>(a, s, t);
        if (t & 1) gRX<3>(a, C[4]);                          // ctrl = global bit 4 (thread)
        gCRX<2, 3>(a, C[3]); gCRX<1, 2>(a, C[2]); gCRX<0, 1>(a, C[1]);
        xpose<1, 2>(a, s, t);                                // to M for coalesced store
#pragma unroll
        for (int r = 0; r < 16; r++) gs[gA(lidx<2>(r, t), cid)] = a[r];
    }
    else if constexpr (PASS == 3) {
        // B map. CRX L0 (0,15), U1 on {12-15}, CRX L1 (15,14)(14,13)(13,12),
        // then U1 on {0-3}, {4-7}.
#pragma unroll
        for (int r = 0; r < 16; r++) a[r] = gs[gB(lidx<0>(r, t), cid)];
        if (t & 1) gRX<3>(a, sC0[0]);                        // ctrl = global bit 0 (thread)
        gU<0>(a, sU[12]); gU<1>(a, sU[13]); gU<2>(a, sU[14]); gU<3>(a, sU[15]);
        gCRX<2, 3>(a, sC1[15]); gCRX<1, 2>(a, sC1[14]); gCRX<0, 1>(a, sC1[13]);
        xpose<0, 1>(a, s, t);
        gU<0>(a, sU[0]); gU<1>(a, sU[1]); gU<2>(a, sU[2]); gU<3>(a, sU[3]);
        xpose<1, 2>(a, s, t);
        gU<0>(a, sU[4]); gU<1>(a, sU[5]); gU<2>(a, sU[6]); gU<3>(a, sU[7]);
#pragma unroll
        for (int r = 0; r < 16; r++) gs[gB(lidx<2>(r, t), cid)] = a[r];
    }
    else {  // PASS == 5
        // B map. CRX L1 (0,15), then measurement (no write-back).
#pragma unroll
        for (int r = 0; r < 16; r++) a[r] = gs[gB(lidx<0>(r, t), cid)];
        if (t & 1) gRX<3>(a, sC1[0]);

        // global bits in this layout: 0-7 = t, 8-11 = cid, 12-15 = r
        float p[16], S = 0.0f;
#pragma unroll
        for (int r = 0; r < 16; r++) {
            float xx, yy; upk(a[r], xx, yy);
            p[r] = xx * xx + yy * yy;
            S += p[r];
        }
        float acc[NQ];
#pragma unroll
        for (int bit = 0; bit < 8; bit++)  acc[bit] = ((t >> bit) & 1) ? -S : S;
#pragma unroll
        for (int bit = 8; bit < 12; bit++) acc[bit] = ((cid >> (bit - 8)) & 1) ? -S : S;
#pragma unroll
        for (int bit = 12; bit < 16; bit++) {
            float v = 0.0f;
#pragma unroll
            for (int r = 0; r < 16; r++) v += ((r >> (bit - 12)) & 1) ? -p[r] : p[r];
            acc[bit] = v;
        }
#pragma unroll
        for (int i = 0; i < NQ; i++) {
#pragma unroll
            for (int o = 16; o >= 1; o >>= 1)
                acc[i] += __shfl_down_sync(0xFFFFFFFFu, acc[i], o);
        }
        __syncthreads();
        int warp = t >> 5, lane = t & 31;
        if (lane == 0) {
#pragma unroll
            for (int i = 0; i < NQ; i++) sred[warp][i] = acc[i];
        }
        __syncthreads();
        if (t < NQ) {
            float sum = 0.0f;
#pragma unroll
            for (int wI = 0; wI < 8; wI++) sum += sred[wI][t];
            g_part[b][cid][t] = sum;      // indexed by BIT
        }
    }
}

// ---------------------------------------------------------------------------
__global__ void k_final(const float* __restrict__ fc_w,
                        const float* __restrict__ fc_b,
                        float* __restrict__ out) {
    int b = blockIdx.x;
    int t = threadIdx.x;
    __shared__ float feats[NQ];
    __shared__ float logits[NCLS];
    if (t < NQ) {
        float sum = 0.0f;
        int bit = 15 - t;                 // wire t measures bit (15 - t)
#pragma unroll
        for (int c = 0; c < NCHUNK; c++) sum += g_part[b][c][bit];
        feats[t] = sum;
    }
    __syncthreads();
    if (t < NCLS) {
        float z = fc_b[t];
#pragma unroll
        for (int wI = 0; wI < NQ; wI++) z += feats[wI] * fc_w[t * NQ + wI];
        logits[t] = z;
    }
    __syncthreads();
    if (t == 0) {
        float mx = logits[0];
        for (int c = 1; c < NCLS; c++) mx = fmaxf(mx, logits[c]);
        float sum = 0.0f;
        for (int c = 0; c < NCLS; c++) sum += expf(logits[c] - mx);
        float l = logf(sum) + mx;
        for (int c = 0; c < NCLS; c++) out[b * NCLS + c] = logits[c] - l;
    }
}

// ---------------------------------------------------------------------------
extern "C" void kernel_launch(void* const* d_in, const int* in_sizes, int n_in,
                              void* d_out, int out_size) {
    const float* x    = (const float*)d_in[0];
    const float* w0   = (const float*)d_in[1];
    const float* x0   = (const float*)d_in[2];
    const float* w1   = (const float*)d_in[3];
    const float* x1   = (const float*)d_in[4];
    const float* fc_w = (const float*)d_in[5];
    const float* fc_b = (const float*)d_in[6];
    float* out = (float*)d_out;

    dim3 grid(NCHUNK, BATCH);
    k_pass<1><<<grid, TPB>>>(x, w0, x0, w1, x1);
    k_pass<2><<<grid, TPB>>>(x, w0, x0, w1, x1);
    k_pass<3><<<grid, TPB>>>(x, w0, x0, w1, x1);
    k_pass<4><<<grid, TPB>>>(x, w0, x0, w1, x1);
    k_pass<5><<<grid, TPB>>>(x, w0, x0, w1, x1);
    k_final<<<BATCH, 32>>>(fc_w, fc_b, out);
}